// round 4
// baseline (speedup 1.0000x reference)
#include <cuda_runtime.h>
#include <stdint.h>

#define NN 8192
#define NE 262144
#define CC 512

// ---------------- device scratch (no allocs allowed) ----------------
__device__ unsigned g_bitmap[(size_t)NN * NN / 32];  // 8 MiB dense adjacency bitmap
__device__ int      g_deg[NN];
__device__ float    g_dis[NN];
__device__ float    g_g[(size_t)NN * CC];            // g[j] = dis[j] * h[j], 16 MiB (L2-resident)

// ---------------- kernel 1: clear bitmap + deg ----------------
// exactly (NN*NN/32)/4 = 524288 threads, one uint4 each
__global__ __launch_bounds__(256) void k_clear() {
    int t = blockIdx.x * blockDim.x + threadIdx.x;
    ((uint4*)g_bitmap)[t] = make_uint4(0u, 0u, 0u, 0u);
    if (t < NN) g_deg[t] = 0;
}

// ---------------- kernel 2: dedup edges (+ self loops) & count degrees ----------------
// edge_index dtype is sniffed at runtime: jnp.int64 silently degrades to int32
// when JAX x64 is disabled. For genuine int64 (values < 8192, little-endian),
// the odd 32-bit words (high halves) of the first elements are all zero.
__global__ __launch_bounds__(256) void k_dedup(const void* __restrict__ eraw) {
    const int* e32 = (const int*)eraw;
    // uniform across all threads (broadcast loads)
    bool is64 = (e32[1] == 0) && (e32[3] == 0) && (e32[5] == 0) && (e32[7] == 0);

    int e = blockIdx.x * blockDim.x + threadIdx.x;
    if (e >= NE + NN) return;
    int r, c;
    if (e < NE) {
        if (is64) {
            const long long* e64 = (const long long*)eraw;
            r = (int)e64[e];         // edge_index[0][e]
            c = (int)e64[NE + e];    // edge_index[1][e]
        } else {
            r = e32[e];
            c = e32[NE + e];
        }
    } else {
        r = c = e - NE;              // self loop
    }
    r &= (NN - 1);                   // hard OOB guard (no-op for valid ids)
    c &= (NN - 1);
    unsigned idx  = (unsigned)r * (unsigned)NN + (unsigned)c;
    unsigned mask = 1u << (idx & 31u);
    unsigned old  = atomicOr(&g_bitmap[idx >> 5], mask);
    if (!(old & mask)) atomicAdd(&g_deg[r], 1);
}

// ---------------- kernel 3: dis = deg^{-1/2} ----------------
__global__ __launch_bounds__(256) void k_dis() {
    int i = blockIdx.x * blockDim.x + threadIdx.x;
    if (i < NN) g_dis[i] = rsqrtf((float)g_deg[i]);  // deg >= 1 (self loop)
}

// ---------------- kernel 4: g[m] = dis[m] * (x W^T + b)[m]  (fp32 SGEMM 128x128x8) ----------------
__global__ __launch_bounds__(256) void k_gemm(const float* __restrict__ x,
                                              const float* __restrict__ W,
                                              const float* __restrict__ b) {
    __shared__ float As[8][128];
    __shared__ float Bs[8][128];
    const int tid = threadIdx.x;
    const int m0  = blockIdx.y * 128;
    const int n0  = blockIdx.x * 128;
    const int lr  = tid >> 1;         // load row 0..127
    const int lk  = (tid & 1) * 4;    // k sub-offset 0 or 4
    const int tx  = tid & 15;
    const int ty  = tid >> 4;

    const float* pa = x + (size_t)(m0 + lr) * CC + lk;
    const float* pb = W + (size_t)(n0 + lr) * CC + lk;

    float acc[8][8];
#pragma unroll
    for (int i = 0; i < 8; i++)
#pragma unroll
        for (int j = 0; j < 8; j++) acc[i][j] = 0.f;

    for (int k0 = 0; k0 < CC; k0 += 8) {
        float4 a4 = *(const float4*)(pa + k0);
        float4 b4 = *(const float4*)(pb + k0);
        As[lk + 0][lr] = a4.x; As[lk + 1][lr] = a4.y;
        As[lk + 2][lr] = a4.z; As[lk + 3][lr] = a4.w;
        Bs[lk + 0][lr] = b4.x; Bs[lk + 1][lr] = b4.y;
        Bs[lk + 2][lr] = b4.z; Bs[lk + 3][lr] = b4.w;
        __syncthreads();
#pragma unroll
        for (int k = 0; k < 8; k++) {
            float4 ra0 = *(const float4*)&As[k][ty * 8];
            float4 ra1 = *(const float4*)&As[k][ty * 8 + 4];
            float4 rb0 = *(const float4*)&Bs[k][tx * 8];
            float4 rb1 = *(const float4*)&Bs[k][tx * 8 + 4];
            float ra[8] = {ra0.x, ra0.y, ra0.z, ra0.w, ra1.x, ra1.y, ra1.z, ra1.w};
            float rb[8] = {rb0.x, rb0.y, rb0.z, rb0.w, rb1.x, rb1.y, rb1.z, rb1.w};
#pragma unroll
            for (int i = 0; i < 8; i++)
#pragma unroll
                for (int j = 0; j < 8; j++)
                    acc[i][j] = fmaf(ra[i], rb[j], acc[i][j]);
        }
        __syncthreads();
    }

#pragma unroll
    for (int i = 0; i < 8; i++) {
        int   m  = m0 + ty * 8 + i;
        float dm = g_dis[m];
#pragma unroll
        for (int j = 0; j < 8; j++) {
            int n = n0 + tx * 8 + j;
            g_g[(size_t)m * CC + n] = dm * (acc[i][j] + b[n]);
        }
    }
}

// ---------------- kernel 5: out[i] = dis[i] * sum_{j in adj(i)} g[j]  ----------------
// One CTA (128 threads) per row. All threads walk the row's bitmap in lockstep
// (identical control flow, ascending j => deterministic, no atomics). Each thread
// owns 4 consecutive channels (float4), so each neighbor gather is a fully
// coalesced 2 KiB read of g[j] out of L2.
__global__ __launch_bounds__(128) void k_spmm(float* __restrict__ out) {
    const int i   = blockIdx.x;
    const int tid = threadIdx.x;
    __shared__ unsigned rowbits[256];  // 8192 bits

    rowbits[tid]       = g_bitmap[(size_t)i * 256 + tid];
    rowbits[tid + 128] = g_bitmap[(size_t)i * 256 + tid + 128];
    __syncthreads();

    const float4* __restrict__ g4 = (const float4*)g_g;
    float4 acc = make_float4(0.f, 0.f, 0.f, 0.f);

    for (int w = 0; w < 256; w++) {
        unsigned bits = rowbits[w];
        while (bits) {
            int j = (w << 5) + __ffs(bits) - 1;
            bits &= bits - 1;
            float4 gv = g4[(size_t)j * (CC / 4) + tid];
            acc.x += gv.x; acc.y += gv.y; acc.z += gv.z; acc.w += gv.w;
        }
    }

    float di = g_dis[i];
    float4 o = make_float4(di * acc.x, di * acc.y, di * acc.z, di * acc.w);
    ((float4*)out)[(size_t)i * (CC / 4) + tid] = o;
}

// ---------------- launch ----------------
extern "C" void kernel_launch(void* const* d_in, const int* in_sizes, int n_in,
                              void* d_out, int out_size) {
    // Identify inputs by element count (robust to ordering):
    //   x: 8192*512 = 4194304, edge_index: 2*262144 = 524288,
    //   W: 512*512 = 262144,  b: 512
    const float* x  = nullptr;
    const void*  ei = nullptr;
    const float* W  = nullptr;
    const float* b  = nullptr;
    for (int i = 0; i < n_in; i++) {
        switch (in_sizes[i]) {
            case 4194304: x  = (const float*)d_in[i]; break;
            case 524288:  ei = d_in[i];               break;
            case 262144:  W  = (const float*)d_in[i]; break;
            case 512:     b  = (const float*)d_in[i]; break;
            default: break;
        }
    }
    float* o = (float*)d_out;

    // 1. clear bitmap + deg: 524288 threads (one uint4 each)
    k_clear<<<2048, 256>>>();
    // 2. dedup + degree over E + N entries (dtype-sniffing inside)
    k_dedup<<<(NE + NN + 255) / 256, 256>>>(ei);
    // 3. dis = rsqrt(deg)
    k_dis<<<(NN + 255) / 256, 256>>>();
    // 4. g = dis * (x W^T + b)
    dim3 ggrid(CC / 128, NN / 128);   // (4, 64)
    k_gemm<<<ggrid, 256>>>(x, W, b);
    // 5. out = dis * (A @ g)
    k_spmm<<<NN, 128>>>(o);
}

// round 7
// speedup vs baseline: 1.9745x; 1.9745x over previous
#include <cuda_runtime.h>
#include <cuda_bf16.h>
#include <stdint.h>

#define NN 8192
#define NE 262144
#define CC 512
#define KCAT 1536   // 3 * 512 split-bf16 K
#define KTILES 24   // KCAT / 64

// ---------------- device scratch ----------------
__device__ unsigned      g_bitmap[(size_t)NN * NN / 32];     // 8 MiB adjacency bitmap
__device__ int           g_deg[NN];
__device__ float         g_dis[NN];
__device__ float         g_g[(size_t)NN * CC];               // dis[m]*(xW^T+b), 16 MiB
__device__ __nv_bfloat16 g_xcat[(size_t)NN * KCAT];          // [xh | xl | xh], 24 MiB
__device__ __nv_bfloat16 g_wcat[(size_t)CC * KCAT];          // [wh | wh | wl], 1.5 MiB

// ---------------- PTX helpers (baseline PTX only: sm_80-era features) ----------------
__device__ __forceinline__ uint32_t smem_u32(const void* p) {
    uint32_t a;
    asm("{ .reg .u64 t; cvta.to.shared.u64 t, %1; cvt.u32.u64 %0, t; }" : "=r"(a) : "l"(p));
    return a;
}
#define CP_ASYNC16(dst, src) \
    asm volatile("cp.async.cg.shared.global [%0], [%1], 16;" :: "r"(dst), "l"(src) : "memory")
#define CP_COMMIT()  asm volatile("cp.async.commit_group;" ::: "memory")
#define CP_WAIT(N)   asm volatile("cp.async.wait_group %0;" :: "n"(N) : "memory")

#define LDM_X4(r, addr)                                                          \
    asm volatile("ldmatrix.sync.aligned.m8n8.x4.shared.b16 {%0,%1,%2,%3}, [%4];" \
        : "=r"((r)[0]), "=r"((r)[1]), "=r"((r)[2]), "=r"((r)[3]) : "r"(addr))

#define MMA16816(d, a, b0v, b1v)                                                  \
    asm volatile("mma.sync.aligned.m16n8k16.row.col.f32.bf16.bf16.f32 "           \
        "{%0,%1,%2,%3}, {%4,%5,%6,%7}, {%8,%9}, {%0,%1,%2,%3};"                   \
        : "+f"((d)[0]), "+f"((d)[1]), "+f"((d)[2]), "+f"((d)[3])                  \
        : "r"((a)[0]), "r"((a)[1]), "r"((a)[2]), "r"((a)[3]), "r"(b0v), "r"(b1v))

// ---------------- kernel 1: clear bitmap + deg ----------------
__global__ __launch_bounds__(256) void k_clear() {
    int t = blockIdx.x * blockDim.x + threadIdx.x;
    ((uint4*)g_bitmap)[t] = make_uint4(0u, 0u, 0u, 0u);
    if (t < NN) g_deg[t] = 0;
}

// ---------------- kernel 2: dedup edges (+ self loops), degrees ----------------
__global__ __launch_bounds__(256) void k_dedup(const void* __restrict__ eraw) {
    const int* e32 = (const int*)eraw;
    bool is64 = (e32[1] == 0) && (e32[3] == 0) && (e32[5] == 0) && (e32[7] == 0);
    int e = blockIdx.x * blockDim.x + threadIdx.x;
    if (e >= NE + NN) return;
    int r, c;
    if (e < NE) {
        if (is64) {
            const long long* e64 = (const long long*)eraw;
            r = (int)e64[e]; c = (int)e64[NE + e];
        } else {
            r = e32[e]; c = e32[NE + e];
        }
    } else {
        r = c = e - NE;
    }
    r &= (NN - 1); c &= (NN - 1);
    unsigned idx  = (unsigned)r * (unsigned)NN + (unsigned)c;
    unsigned mask = 1u << (idx & 31u);
    unsigned old  = atomicOr(&g_bitmap[idx >> 5], mask);
    if (!(old & mask)) atomicAdd(&g_deg[r], 1);
}

// ---------------- kernel 3: dis = deg^{-1/2} ----------------
__global__ __launch_bounds__(256) void k_dis() {
    int i = blockIdx.x * blockDim.x + threadIdx.x;
    if (i < NN) g_dis[i] = rsqrtf((float)g_deg[i]);
}

// ---------------- kernel 4a/4b: bf16 hi/lo split concat ----------------
__global__ __launch_bounds__(256) void k_convX(const float* __restrict__ x) {
    int t = blockIdx.x * blockDim.x + threadIdx.x;   // NN*CC threads
    int m = t >> 9, k = t & 511;
    float v = x[t];
    __nv_bfloat16 h = __float2bfloat16(v);
    __nv_bfloat16 l = __float2bfloat16(v - __bfloat162float(h));
    size_t rb = (size_t)m * KCAT;
    g_xcat[rb + k]        = h;   // block0: xh
    g_xcat[rb + 512 + k]  = l;   // block1: xl
    g_xcat[rb + 1024 + k] = h;   // block2: xh
}
__global__ __launch_bounds__(256) void k_convW(const float* __restrict__ W) {
    int t = blockIdx.x * blockDim.x + threadIdx.x;   // CC*CC threads
    int n = t >> 9, k = t & 511;
    float v = W[t];
    __nv_bfloat16 h = __float2bfloat16(v);
    __nv_bfloat16 l = __float2bfloat16(v - __bfloat162float(h));
    size_t rb = (size_t)n * KCAT;
    g_wcat[rb + k]        = h;   // pairs xh -> xh*wh
    g_wcat[rb + 512 + k]  = h;   // pairs xl -> xl*wh
    g_wcat[rb + 1024 + k] = l;   // pairs xh -> xh*wl
}

// ---------------- kernel 5: mma.sync GEMM  g = dis * (xcat @ wcat^T + b) ----------------
// CTA tile 128(M) x 128(N) x 64(K), 256 threads = 8 warps (4 M x 2 N),
// warp tile 32x64, m16n8k16 bf16 HMMA, cp.async double buffer.
// smem tile: [128 rows][8 x 16B units], phys unit = c16 ^ (row & 7)  (conflict-free
// for both the cp.async stores and the ldmatrix reads).
__device__ __forceinline__ void gemm_load_stage(uint32_t sbase, int stage, int kt,
                                                const __nv_bfloat16* xa0,
                                                const __nv_bfloat16* wa0, int tid) {
    const __nv_bfloat16* xa = xa0 + kt * 64;
    const __nv_bfloat16* wa = wa0 + kt * 64;
    uint32_t abase = sbase + stage * 32768;
    uint32_t bbase = abase + 16384;
#pragma unroll
    for (int j = 0; j < 4; j++) {
        int u = tid * 4 + j;               // 0..1023 : 128 rows x 8 units
        int row = u >> 3, c16 = u & 7;
        uint32_t phys = (uint32_t)(c16 ^ (row & 7));
        uint32_t so   = row * 128 + phys * 16;
        CP_ASYNC16(abase + so, xa + (size_t)row * KCAT + c16 * 8);
        CP_ASYNC16(bbase + so, wa + (size_t)row * KCAT + c16 * 8);
    }
    CP_COMMIT();
}

__global__ __launch_bounds__(256) void k_gemm_mma(const float* __restrict__ b) {
    extern __shared__ char sm[];
    const int tid    = threadIdx.x;
    const int wid    = tid >> 5;
    const int lane   = tid & 31;
    const int warp_m = wid & 3;        // 0..3 -> 32-row slices
    const int warp_n = wid >> 2;       // 0..1 -> 64-col slices
    const int n0     = blockIdx.x * 128;
    const int m0     = blockIdx.y * 128;
    const uint32_t sbase = smem_u32(sm);

    const __nv_bfloat16* xa0 = g_xcat + (size_t)m0 * KCAT;
    const __nv_bfloat16* wa0 = g_wcat + (size_t)n0 * KCAT;

    float acc[2][8][4];
#pragma unroll
    for (int mt = 0; mt < 2; mt++)
#pragma unroll
        for (int nt = 0; nt < 8; nt++)
#pragma unroll
            for (int q = 0; q < 4; q++) acc[mt][nt][q] = 0.f;

    gemm_load_stage(sbase, 0, 0, xa0, wa0, tid);
    gemm_load_stage(sbase, 1, 1, xa0, wa0, tid);

    const int lrow = lane & 15;     // ldmatrix row-within-16
    const int lhalf = lane >> 4;    // k 16B-unit half

    for (int kt = 0; kt < KTILES; kt++) {
        if (kt >= KTILES - 2) { CP_WAIT(0); } else { CP_WAIT(1); }
        __syncthreads();

        int      stage = kt & 1;
        uint32_t abase = sbase + stage * 32768;
        uint32_t bbase = abase + 16384;

#pragma unroll
        for (int ks = 0; ks < 4; ks++) {
            int c16 = ks * 2 + lhalf;
            uint32_t ra[2][4], rbp[4][4];
#pragma unroll
            for (int mt = 0; mt < 2; mt++) {
                int row = warp_m * 32 + mt * 16 + lrow;
                LDM_X4(ra[mt], abase + row * 128 + ((c16 ^ (row & 7)) << 4));
            }
#pragma unroll
            for (int np = 0; np < 4; np++) {
                int row = warp_n * 64 + np * 16 + lrow;
                LDM_X4(rbp[np], bbase + row * 128 + ((c16 ^ (row & 7)) << 4));
            }
#pragma unroll
            for (int mt = 0; mt < 2; mt++)
#pragma unroll
                for (int nt = 0; nt < 8; nt++) {
                    int p = nt >> 1, s = nt & 1;
                    MMA16816(acc[mt][nt], ra[mt], rbp[p][s], rbp[p][s + 2]);
                }
        }
        __syncthreads();
        if (kt + 2 < KTILES) gemm_load_stage(sbase, stage, kt + 2, xa0, wa0, tid);
    }

    // epilogue: acc -> g_g with dis[m] scale and b[n] bias.
    // c fragment: rows lane>>2 (+8), cols (lane&3)*2 (+1)  -> float2 stores.
#pragma unroll
    for (int mt = 0; mt < 2; mt++) {
        int   r0 = m0 + warp_m * 32 + mt * 16 + (lane >> 2);
        int   r1 = r0 + 8;
        float d0 = g_dis[r0], d1 = g_dis[r1];
#pragma unroll
        for (int nt = 0; nt < 8; nt++) {
            int   nc = n0 + warp_n * 64 + nt * 8 + (lane & 3) * 2;
            float b0 = b[nc], b1 = b[nc + 1];
            float2 v0 = make_float2(d0 * (acc[mt][nt][0] + b0), d0 * (acc[mt][nt][1] + b1));
            float2 v1 = make_float2(d1 * (acc[mt][nt][2] + b0), d1 * (acc[mt][nt][3] + b1));
            *(float2*)&g_g[(size_t)r0 * CC + nc] = v0;
            *(float2*)&g_g[(size_t)r1 * CC + nc] = v1;
        }
    }
}

// ---------------- kernel 6: SpMM  out[i] = dis[i] * sum_{j in adj(i)} g[j] ----------------
// Bitmap row -> ordered index list in smem (popc + warp scan, deterministic,
// ascending), then 4-way unrolled gather for MLP. Fallback to lockstep bitmap
// walk if a row is pathologically dense (>1024 neighbors).
__global__ __launch_bounds__(128) void k_spmm(float* __restrict__ out) {
    const int i    = blockIdx.x;
    const int tid  = threadIdx.x;
    const int lane = tid & 31;
    const int w    = tid >> 5;
    __shared__ unsigned rb[256];
    __shared__ int      sidx[1024];
    __shared__ int      wtot[4];

    rb[tid]       = g_bitmap[(size_t)i * 256 + tid];
    rb[tid + 128] = g_bitmap[(size_t)i * 256 + tid + 128];
    __syncthreads();

    unsigned w0 = rb[2 * tid], w1 = rb[2 * tid + 1];
    int cnt = __popc(w0) + __popc(w1);
    int inc = cnt;
#pragma unroll
    for (int o = 1; o < 32; o <<= 1) {
        int v = __shfl_up_sync(0xFFFFFFFFu, inc, o);
        if (lane >= o) inc += v;
    }
    if (lane == 31) wtot[w] = inc;
    __syncthreads();
    int base = inc - cnt;
    for (int q = 0; q < w; q++) base += wtot[q];
    int total = wtot[0] + wtot[1] + wtot[2] + wtot[3];

    const float4* __restrict__ g4 = (const float4*)g_g;
    float4 acc = make_float4(0.f, 0.f, 0.f, 0.f);
    float  di  = g_dis[i];

    if (total <= 1024) {
        int pos = base, jb = tid * 64;
        unsigned bb = w0;
        while (bb) { sidx[pos++] = jb + __ffs(bb) - 1; bb &= bb - 1; }
        bb = w1; jb += 32;
        while (bb) { sidx[pos++] = jb + __ffs(bb) - 1; bb &= bb - 1; }
        __syncthreads();

        int p = 0;
        for (; p + 4 <= total; p += 4) {
            int i0 = sidx[p], i1 = sidx[p + 1], i2 = sidx[p + 2], i3 = sidx[p + 3];
            float4 a0 = g4[(size_t)i0 * (CC / 4) + tid];
            float4 a1 = g4[(size_t)i1 * (CC / 4) + tid];
            float4 a2 = g4[(size_t)i2 * (CC / 4) + tid];
            float4 a3 = g4[(size_t)i3 * (CC / 4) + tid];
            acc.x += (a0.x + a1.x) + (a2.x + a3.x);
            acc.y += (a0.y + a1.y) + (a2.y + a3.y);
            acc.z += (a0.z + a1.z) + (a2.z + a3.z);
            acc.w += (a0.w + a1.w) + (a2.w + a3.w);
        }
        for (; p < total; p++) {
            float4 a0 = g4[(size_t)sidx[p] * (CC / 4) + tid];
            acc.x += a0.x; acc.y += a0.y; acc.z += a0.z; acc.w += a0.w;
        }
    } else {
        // lockstep bitmap walk (deterministic ascending order)
        for (int ww = 0; ww < 256; ww++) {
            unsigned bits = rb[ww];
            while (bits) {
                int j = (ww << 5) + __ffs(bits) - 1;
                bits &= bits - 1;
                float4 gv = g4[(size_t)j * (CC / 4) + tid];
                acc.x += gv.x; acc.y += gv.y; acc.z += gv.z; acc.w += gv.w;
            }
        }
    }

    ((float4*)out)[(size_t)i * (CC / 4) + tid] =
        make_float4(di * acc.x, di * acc.y, di * acc.z, di * acc.w);
}

// ---------------- launch ----------------
extern "C" void kernel_launch(void* const* d_in, const int* in_sizes, int n_in,
                              void* d_out, int out_size) {
    const float* x  = nullptr;
    const void*  ei = nullptr;
    const float* W  = nullptr;
    const float* b  = nullptr;
    for (int i = 0; i < n_in; i++) {
        switch (in_sizes[i]) {
            case 4194304: x  = (const float*)d_in[i]; break;
            case 524288:  ei = d_in[i];               break;
            case 262144:  W  = (const float*)d_in[i]; break;
            case 512:     b  = (const float*)d_in[i]; break;
            default: break;
        }
    }
    float* o = (float*)d_out;

    cudaFuncSetAttribute(k_gemm_mma, cudaFuncAttributeMaxDynamicSharedMemorySize, 65536);

    k_clear<<<2048, 256>>>();
    k_dedup<<<(NE + NN + 255) / 256, 256>>>(ei);
    k_dis<<<(NN + 255) / 256, 256>>>();
    k_convX<<<(NN * CC) / 256, 256>>>(x);
    k_convW<<<(CC * CC) / 256, 256>>>(W);
    dim3 ggrid(CC / 128, NN / 128);   // (4, 64)
    k_gemm_mma<<<ggrid, 256, 65536>>>(b);
    k_spmm<<<NN, 128>>>(o);
}

// round 9
// speedup vs baseline: 2.1549x; 1.0913x over previous
#include <cuda_runtime.h>
#include <cuda_bf16.h>
#include <stdint.h>

#define NN 8192
#define NE 262144
#define CC 512
#define KX   1024   // x split: [xh | xl]
#define KW   1536   // w split: [wh | wh | wl]
#define KTILES 24   // KW / 64 (x k-tiles 16..23 remap to block0 = xh)

// ---------------- device scratch ----------------
__device__ unsigned      g_bitmap[(size_t)NN * NN / 32];     // 8 MiB adjacency bitmap
__device__ int           g_deg[NN];
__device__ float         g_dis[NN];
__device__ float         g_g[(size_t)NN * CC];               // dis[m]*(xW^T+b), 16 MiB
__device__ __nv_bfloat16 g_xcat[(size_t)NN * KX];            // [xh | xl], 16 MiB
__device__ __nv_bfloat16 g_wcat[(size_t)CC * KW];            // [wh | wh | wl], 1.5 MiB

// ---------------- PTX helpers (baseline PTX only: sm_80-era features) ----------------
__device__ __forceinline__ uint32_t smem_u32(const void* p) {
    uint32_t a;
    asm("{ .reg .u64 t; cvta.to.shared.u64 t, %1; cvt.u32.u64 %0, t; }" : "=r"(a) : "l"(p));
    return a;
}
#define CP_ASYNC16(dst, src) \
    asm volatile("cp.async.cg.shared.global [%0], [%1], 16;" :: "r"(dst), "l"(src) : "memory")
#define CP_COMMIT()  asm volatile("cp.async.commit_group;" ::: "memory")
#define CP_WAIT(N)   asm volatile("cp.async.wait_group %0;" :: "n"(N) : "memory")

#define LDM_X4(r, addr)                                                          \
    asm volatile("ldmatrix.sync.aligned.m8n8.x4.shared.b16 {%0,%1,%2,%3}, [%4];" \
        : "=r"((r)[0]), "=r"((r)[1]), "=r"((r)[2]), "=r"((r)[3]) : "r"(addr))

#define MMA16816(d, a, b0v, b1v)                                                  \
    asm volatile("mma.sync.aligned.m16n8k16.row.col.f32.bf16.bf16.f32 "           \
        "{%0,%1,%2,%3}, {%4,%5,%6,%7}, {%8,%9}, {%0,%1,%2,%3};"                   \
        : "+f"((d)[0]), "+f"((d)[1]), "+f"((d)[2]), "+f"((d)[3])                  \
        : "r"((a)[0]), "r"((a)[1]), "r"((a)[2]), "r"((a)[3]), "r"(b0v), "r"(b1v))

// ---------------- kernel 1: clear bitmap + deg ----------------
__global__ __launch_bounds__(256) void k_clear() {
    int t = blockIdx.x * blockDim.x + threadIdx.x;
    ((uint4*)g_bitmap)[t] = make_uint4(0u, 0u, 0u, 0u);
    if (t < NN) g_deg[t] = 0;
}

// ---------------- kernel 2: dedup edges (+ self loops), degrees ----------------
__global__ __launch_bounds__(256) void k_dedup(const void* __restrict__ eraw) {
    const int* e32 = (const int*)eraw;
    bool is64 = (e32[1] == 0) && (e32[3] == 0) && (e32[5] == 0) && (e32[7] == 0);
    int e = blockIdx.x * blockDim.x + threadIdx.x;
    if (e >= NE + NN) return;
    int r, c;
    if (e < NE) {
        if (is64) {
            const long long* e64 = (const long long*)eraw;
            r = (int)e64[e]; c = (int)e64[NE + e];
        } else {
            r = e32[e]; c = e32[NE + e];
        }
    } else {
        r = c = e - NE;
    }
    r &= (NN - 1); c &= (NN - 1);
    unsigned idx  = (unsigned)r * (unsigned)NN + (unsigned)c;
    unsigned mask = 1u << (idx & 31u);
    unsigned old  = atomicOr(&g_bitmap[idx >> 5], mask);
    if (!(old & mask)) atomicAdd(&g_deg[r], 1);
}

// ---------------- kernel 3 (fused): dis + convX + convW, vectorized ----------------
// convX needs NN*CC/4 = 1048576 threads -> blocks [0, 4096)
// convW needs CC*CC/4 =   65536 threads -> blocks [4096, 4352)   (256 blocks!)
// dis   needs NN      =    8192 threads -> blocks [4352, 4384)
__device__ __forceinline__ void split4(float4 v, uint2& hp, uint2& lp) {
    __nv_bfloat16 h0 = __float2bfloat16(v.x), h1 = __float2bfloat16(v.y);
    __nv_bfloat16 h2 = __float2bfloat16(v.z), h3 = __float2bfloat16(v.w);
    __nv_bfloat16 l0 = __float2bfloat16(v.x - __bfloat162float(h0));
    __nv_bfloat16 l1 = __float2bfloat16(v.y - __bfloat162float(h1));
    __nv_bfloat16 l2 = __float2bfloat16(v.z - __bfloat162float(h2));
    __nv_bfloat16 l3 = __float2bfloat16(v.w - __bfloat162float(h3));
    union { __nv_bfloat162 b[2]; uint2 u; } H, L;
    H.b[0] = __halves2bfloat162(h0, h1); H.b[1] = __halves2bfloat162(h2, h3);
    L.b[0] = __halves2bfloat162(l0, l1); L.b[1] = __halves2bfloat162(l2, l3);
    hp = H.u; lp = L.u;
}
__global__ __launch_bounds__(256) void k_prep(const float* __restrict__ x,
                                              const float* __restrict__ W) {
    int bid = blockIdx.x;
    if (bid < 4096) {                         // ---- convX ----
        int t = bid * 256 + threadIdx.x;      // 0 .. NN*CC/4-1
        int e = t * 4;
        int m = e >> 9, k = e & 511;
        uint2 hp, lp;
        split4(*(const float4*)(x + e), hp, lp);
        size_t rb = (size_t)m * KX;
        *(uint2*)&g_xcat[rb + k]       = hp;  // block0: xh
        *(uint2*)&g_xcat[rb + 512 + k] = lp;  // block1: xl
    } else if (bid < 4352) {                  // ---- convW ----
        int t = (bid - 4096) * 256 + threadIdx.x;  // 0 .. CC*CC/4-1
        int e = t * 4;
        int n = e >> 9, k = e & 511;
        uint2 hp, lp;
        split4(*(const float4*)(W + e), hp, lp);
        size_t rb = (size_t)n * KW;
        *(uint2*)&g_wcat[rb + k]        = hp; // pairs xh -> xh*wh
        *(uint2*)&g_wcat[rb + 512 + k]  = hp; // pairs xl -> xl*wh
        *(uint2*)&g_wcat[rb + 1024 + k] = lp; // pairs xh -> xh*wl
    } else {                                  // ---- dis ----
        int i = (bid - 4352) * 256 + threadIdx.x;
        if (i < NN) g_dis[i] = rsqrtf((float)g_deg[i]);
    }
}

// ---------------- kernel 4: mma.sync GEMM  g = dis * (split(x) @ split(W)^T + b) ----------------
// CTA tile 128(M) x 128(N) x 64(K), 256 threads = 8 warps (4 M x 2 N),
// warp tile 32x64, m16n8k16 bf16 HMMA, cp.async 3-stage pipeline.
// smem tile: [128 rows][8 x 16B units], phys unit = c16 ^ (row & 7).
__device__ __forceinline__ void gemm_load_stage(uint32_t sbase, int stage, int kt,
                                                const __nv_bfloat16* xa0,
                                                const __nv_bfloat16* wa0, int tid) {
    int xkt = (kt < 16) ? kt : kt - 16;       // k-tiles 16..23 reuse xh block
    const __nv_bfloat16* xa = xa0 + xkt * 64;
    const __nv_bfloat16* wa = wa0 + kt * 64;
    uint32_t abase = sbase + stage * 32768;
    uint32_t bbase = abase + 16384;
#pragma unroll
    for (int j = 0; j < 4; j++) {
        int u = tid * 4 + j;                  // 0..1023 : 128 rows x 8 units
        int row = u >> 3, c16 = u & 7;
        uint32_t so = row * 128 + ((uint32_t)(c16 ^ (row & 7)) << 4);
        CP_ASYNC16(abase + so, xa + (size_t)row * KX + c16 * 8);
        CP_ASYNC16(bbase + so, wa + (size_t)row * KW + c16 * 8);
    }
    CP_COMMIT();
}

__global__ __launch_bounds__(256) void k_gemm_mma(const float* __restrict__ b) {
    extern __shared__ char sm[];
    const int tid    = threadIdx.x;
    const int wid    = tid >> 5;
    const int lane   = tid & 31;
    const int warp_m = wid & 3;
    const int warp_n = wid >> 2;
    const int n0     = blockIdx.x * 128;
    const int m0     = blockIdx.y * 128;
    const uint32_t sbase = smem_u32(sm);

    const __nv_bfloat16* xa0 = g_xcat + (size_t)m0 * KX;
    const __nv_bfloat16* wa0 = g_wcat + (size_t)n0 * KW;

    float acc[2][8][4];
#pragma unroll
    for (int mt = 0; mt < 2; mt++)
#pragma unroll
        for (int nt = 0; nt < 8; nt++)
#pragma unroll
            for (int q = 0; q < 4; q++) acc[mt][nt][q] = 0.f;

    gemm_load_stage(sbase, 0, 0, xa0, wa0, tid);
    gemm_load_stage(sbase, 1, 1, xa0, wa0, tid);
    gemm_load_stage(sbase, 2, 2, xa0, wa0, tid);

    const int lrow  = lane & 15;
    const int lhalf = lane >> 4;

#pragma unroll 1
    for (int kt = 0; kt < KTILES; kt++) {
        if (kt < KTILES - 2)       { CP_WAIT(2); }
        else if (kt == KTILES - 2) { CP_WAIT(1); }
        else                       { CP_WAIT(0); }
        __syncthreads();

        int      stage = kt % 3;
        uint32_t abase = sbase + stage * 32768;
        uint32_t bbase = abase + 16384;

#pragma unroll
        for (int ks = 0; ks < 4; ks++) {
            int c16 = ks * 2 + lhalf;
            uint32_t ra[2][4], rbp[4][4];
#pragma unroll
            for (int mt = 0; mt < 2; mt++) {
                int row = warp_m * 32 + mt * 16 + lrow;
                LDM_X4(ra[mt], abase + row * 128 + ((c16 ^ (row & 7)) << 4));
            }
#pragma unroll
            for (int np = 0; np < 4; np++) {
                int row = warp_n * 64 + np * 16 + lrow;
                LDM_X4(rbp[np], bbase + row * 128 + ((c16 ^ (row & 7)) << 4));
            }
#pragma unroll
            for (int mt = 0; mt < 2; mt++)
#pragma unroll
                for (int nt = 0; nt < 8; nt++) {
                    int p = nt >> 1, s = nt & 1;
                    MMA16816(acc[mt][nt], ra[mt], rbp[p][s], rbp[p][s + 2]);
                }
        }
        __syncthreads();
        if (kt + 3 < KTILES) gemm_load_stage(sbase, stage, kt + 3, xa0, wa0, tid);
    }

    // epilogue: acc -> g_g with dis[m] scale and b[n] bias.
#pragma unroll
    for (int mt = 0; mt < 2; mt++) {
        int   r0 = m0 + warp_m * 32 + mt * 16 + (lane >> 2);
        int   r1 = r0 + 8;
        float d0 = g_dis[r0], d1 = g_dis[r1];
#pragma unroll
        for (int nt = 0; nt < 8; nt++) {
            int   nc = n0 + warp_n * 64 + nt * 8 + (lane & 3) * 2;
            float b0 = b[nc], b1 = b[nc + 1];
            float2 v0 = make_float2(d0 * (acc[mt][nt][0] + b0), d0 * (acc[mt][nt][1] + b1));
            float2 v1 = make_float2(d1 * (acc[mt][nt][2] + b0), d1 * (acc[mt][nt][3] + b1));
            *(float2*)&g_g[(size_t)r0 * CC + nc] = v0;
            *(float2*)&g_g[(size_t)r1 * CC + nc] = v1;
        }
    }
}

// ---------------- kernel 5: SpMM  out[i] = dis[i] * sum_{j in adj(i)} g[j] ----------------
__global__ __launch_bounds__(128) void k_spmm(float* __restrict__ out) {
    const int i    = blockIdx.x;
    const int tid  = threadIdx.x;
    const int lane = tid & 31;
    const int w    = tid >> 5;
    __shared__ unsigned rb[256];
    __shared__ int      sidx[1024];
    __shared__ int      wtot[4];

    rb[tid]       = g_bitmap[(size_t)i * 256 + tid];
    rb[tid + 128] = g_bitmap[(size_t)i * 256 + tid + 128];
    __syncthreads();

    unsigned w0 = rb[2 * tid], w1 = rb[2 * tid + 1];
    int cnt = __popc(w0) + __popc(w1);
    int inc = cnt;
#pragma unroll
    for (int o = 1; o < 32; o <<= 1) {
        int v = __shfl_up_sync(0xFFFFFFFFu, inc, o);
        if (lane >= o) inc += v;
    }
    if (lane == 31) wtot[w] = inc;
    __syncthreads();
    int base = inc - cnt;
    for (int q = 0; q < w; q++) base += wtot[q];
    int total = wtot[0] + wtot[1] + wtot[2] + wtot[3];

    const float4* __restrict__ g4 = (const float4*)g_g;
    float4 acc = make_float4(0.f, 0.f, 0.f, 0.f);
    float  di  = g_dis[i];

    if (total <= 1024) {
        int pos = base, jb = tid * 64;
        unsigned bb = w0;
        while (bb) { sidx[pos++] = jb + __ffs(bb) - 1; bb &= bb - 1; }
        bb = w1; jb += 32;
        while (bb) { sidx[pos++] = jb + __ffs(bb) - 1; bb &= bb - 1; }
        __syncthreads();

        int p = 0;
        for (; p + 8 <= total; p += 8) {
            float4 a0 = g4[(size_t)sidx[p + 0] * (CC / 4) + tid];
            float4 a1 = g4[(size_t)sidx[p + 1] * (CC / 4) + tid];
            float4 a2 = g4[(size_t)sidx[p + 2] * (CC / 4) + tid];
            float4 a3 = g4[(size_t)sidx[p + 3] * (CC / 4) + tid];
            float4 a4 = g4[(size_t)sidx[p + 4] * (CC / 4) + tid];
            float4 a5 = g4[(size_t)sidx[p + 5] * (CC / 4) + tid];
            float4 a6 = g4[(size_t)sidx[p + 6] * (CC / 4) + tid];
            float4 a7 = g4[(size_t)sidx[p + 7] * (CC / 4) + tid];
            acc.x += ((a0.x + a1.x) + (a2.x + a3.x)) + ((a4.x + a5.x) + (a6.x + a7.x));
            acc.y += ((a0.y + a1.y) + (a2.y + a3.y)) + ((a4.y + a5.y) + (a6.y + a7.y));
            acc.z += ((a0.z + a1.z) + (a2.z + a3.z)) + ((a4.z + a5.z) + (a6.z + a7.z));
            acc.w += ((a0.w + a1.w) + (a2.w + a3.w)) + ((a4.w + a5.w) + (a6.w + a7.w));
        }
        for (; p < total; p++) {
            float4 a0 = g4[(size_t)sidx[p] * (CC / 4) + tid];
            acc.x += a0.x; acc.y += a0.y; acc.z += a0.z; acc.w += a0.w;
        }
    } else {
        for (int ww = 0; ww < 256; ww++) {
            unsigned bits = rb[ww];
            while (bits) {
                int j = (ww << 5) + __ffs(bits) - 1;
                bits &= bits - 1;
                float4 gv = g4[(size_t)j * (CC / 4) + tid];
                acc.x += gv.x; acc.y += gv.y; acc.z += gv.z; acc.w += gv.w;
            }
        }
    }

    ((float4*)out)[(size_t)i * (CC / 4) + tid] =
        make_float4(di * acc.x, di * acc.y, di * acc.z, di * acc.w);
}

// ---------------- launch ----------------
extern "C" void kernel_launch(void* const* d_in, const int* in_sizes, int n_in,
                              void* d_out, int out_size) {
    const float* x  = nullptr;
    const void*  ei = nullptr;
    const float* W  = nullptr;
    const float* b  = nullptr;
    for (int i = 0; i < n_in; i++) {
        switch (in_sizes[i]) {
            case 4194304: x  = (const float*)d_in[i]; break;
            case 524288:  ei = d_in[i];               break;
            case 262144:  W  = (const float*)d_in[i]; break;
            case 512:     b  = (const float*)d_in[i]; break;
            default: break;
        }
    }
    float* o = (float*)d_out;

    cudaFuncSetAttribute(k_gemm_mma, cudaFuncAttributeMaxDynamicSharedMemorySize, 98304);

    k_clear<<<2048, 256>>>();
    k_dedup<<<(NE + NN + 255) / 256, 256>>>(ei);
    k_prep<<<4384, 256>>>(x, W);              // convX [0,4096) | convW [4096,4352) | dis [4352,4384)
    dim3 ggrid(CC / 128, NN / 128);           // (4, 64)
    k_gemm_mma<<<ggrid, 256, 98304>>>(b);
    k_spmm<<<NN, 128>>>(o);
}